// round 1
// baseline (speedup 1.0000x reference)
#include <cuda_runtime.h>
#include <cuda_bf16.h>

#define BATCH 4
#define MPER  4096
#define NTOT  (BATCH * MPER)
#define PAD_I (-999)
#define PAD_F (-999.0f)
#define CUTOFF 7.0f

// Gathered coordinates: x, y, z, sq (sq replaced by 3e30 marker when invalid)
__device__ float4 g_gat[NTOT];

// ---------------------------------------------------------------------------
// Kernel 1: gather coords (+sq), write partner columns (out cols 2..7)
// ---------------------------------------------------------------------------
__global__ void ff_prep(const float* __restrict__ coords,
                        const int*   __restrict__ abatch,
                        const int*   __restrict__ cidx,
                        const int*   __restrict__ partners,
                        float*       __restrict__ out) {
    int i = blockIdx.x * blockDim.x + threadIdx.x;
    if (i >= NTOT) return;

    int b  = abatch[i];
    int ci = cidx[i];
    const float* cp = coords + ((long)b * MPER + ci) * 3;
    float x = cp[0], y = cp[1], z = cp[2];
    float sq = (x * x + y * y) + z * z;          // mimic reference sum order
    bool valid = (x != PAD_F);
    g_gat[i] = make_float4(x, y, z, valid ? sq : 3e30f);

    // partners: two partners, each -> 3 output floats at cols 2..4 and 5..7
    #pragma unroll
    for (int k = 0; k < 2; k++) {
        int p = partners[i * 2 + k];
        float px, py, pz;
        if (p == PAD_I) {
            px = PAD_F; py = PAD_F; pz = PAD_F;
        } else {
            const float* pp = coords + ((long)b * MPER + p) * 3;
            px = pp[0]; py = pp[1]; pz = pp[2];
        }
        float* o = out + (long)i * 8 + 2 + 3 * k;
        o[0] = px; o[1] = py; o[2] = pz;
    }
}

// ---------------------------------------------------------------------------
// Kernel 2: neighbor distance row-sum with cutoff (out col 1)
//   grid = BATCH*32 blocks, 128 threads; each thread owns one i-row,
//   batch coords streamed through smem in 2 chunks of 2048 float4 (32KB).
// ---------------------------------------------------------------------------
#define PT_THREADS 128
#define PT_CHUNK   2048

__global__ void __launch_bounds__(PT_THREADS)
ff_pairs(float* __restrict__ out) {
    __shared__ float4 sh[PT_CHUNK];

    int b    = blockIdx.x >> 5;       // /32
    int tile = blockIdx.x & 31;
    int base = b * MPER;
    int il   = tile * PT_THREADS + threadIdx.x;
    int ig   = base + il;

    float4 me = g_gat[ig];
    float  msq = me.w;
    float  sum = 0.0f;

    for (int c = 0; c < 2; c++) {
        __syncthreads();
        for (int t = threadIdx.x; t < PT_CHUNK; t += PT_THREADS)
            sh[t] = g_gat[base + c * PT_CHUNK + t];
        __syncthreads();

        #pragma unroll 8
        for (int j = 0; j < PT_CHUNK; j++) {
            float4 o = sh[j];
            float dot = me.x * o.x + me.y * o.y + me.z * o.z;
            float s   = msq + o.w;
            float d2  = fmaf(-2.0f, dot, s);       // mimic sq_i+sq_j-2*dot
            float dm  = fmaxf(d2, 0.0f) + 1e-12f;
            float dist = sqrtf(dm);
            if (dist <= CUTOFF) sum += dist;
        }
    }
    out[(long)ig * 8 + 1] = sum;
}

// ---------------------------------------------------------------------------
// Kernel 3: dihedral angles (out col 0)
// ---------------------------------------------------------------------------
__device__ __forceinline__ float3 f3sub(float4 a, float4 b) {
    return make_float3(a.x - b.x, a.y - b.y, a.z - b.z);
}
__device__ __forceinline__ float3 f3cross(float3 a, float3 b) {
    return make_float3(a.y * b.z - a.z * b.y,
                       a.z * b.x - a.x * b.z,
                       a.x * b.y - a.y * b.x);
}
__device__ __forceinline__ float f3dot(float3 a, float3 b) {
    return a.x * b.x + a.y * b.y + a.z * b.z;
}

__global__ void ff_dihedral(const int* __restrict__ aidx,
                            float*     __restrict__ out) {
    int i = blockIdx.x * blockDim.x + threadIdx.x;
    if (i >= NTOT) return;

    int i0 = aidx[i * 4 + 0];
    int i1 = aidx[i * 4 + 1];
    int i2 = aidx[i * 4 + 2];
    int i3 = aidx[i * 4 + 3];

    if (i0 == PAD_I || i1 == PAD_I || i2 == PAD_I || i3 == PAD_I) {
        out[(long)i * 8] = PAD_F;
        return;
    }

    float4 p1 = g_gat[i0];
    float4 p2 = g_gat[i1];
    float4 p3 = g_gat[i2];
    float4 p4 = g_gat[i3];

    float3 b1 = f3sub(p2, p1);
    float3 b2 = f3sub(p3, p2);
    float3 b3 = f3sub(p4, p3);

    float3 n1 = f3cross(b1, b2);
    float3 n2 = f3cross(b2, b3);

    float nb2 = sqrtf((b2.x * b2.x + b2.y * b2.y) + b2.z * b2.z);
    float inv = 1.0f / (nb2 + 1e-12f);
    float3 b2n = make_float3(b2.x * inv, b2.y * inv, b2.z * inv);

    float3 m1 = f3cross(n1, b2n);

    float xv = f3dot(n1, n2);
    float yv = f3dot(m1, n2);

    out[(long)i * 8] = atan2f(yv, xv);
}

// ---------------------------------------------------------------------------
extern "C" void kernel_launch(void* const* d_in, const int* in_sizes, int n_in,
                              void* d_out, int out_size) {
    const float* coords   = (const float*)d_in[0];
    const int*   abatch   = (const int*)  d_in[1];
    const int*   cidx     = (const int*)  d_in[2];
    const int*   partners = (const int*)  d_in[3];
    const int*   aidx     = (const int*)  d_in[4];
    float*       out      = (float*)d_out;

    ff_prep<<<(NTOT + 255) / 256, 256>>>(coords, abatch, cidx, partners, out);
    ff_pairs<<<BATCH * 32, PT_THREADS>>>(out);
    ff_dihedral<<<(NTOT + 255) / 256, 256>>>(aidx, out);
}

// round 3
// speedup vs baseline: 5.4995x; 5.4995x over previous
#include <cuda_runtime.h>
#include <cuda_bf16.h>

#define BATCH 4
#define MPER  4096
#define NTOT  (BATCH * MPER)
#define PAD_I (-999)
#define PAD_F (-999.0f)
#define CUTOFF 7.0f

// Gathered coordinates: x, y, z, sq (sq replaced by 3e30 marker when invalid)
__device__ float4 g_gat[NTOT];

// Partial row-sums for the pair kernel: [JSPLIT][NTOT]
#define JSPLIT 16
#define JCHUNK (MPER / JSPLIT)        // 256
__device__ float g_partial[JSPLIT * NTOT];

// ---------------------------------------------------------------------------
// Kernel 1: gather coords (+sq), write partner columns (out cols 2..7)
// ---------------------------------------------------------------------------
__global__ void ff_prep(const float* __restrict__ coords,
                        const int*   __restrict__ abatch,
                        const int*   __restrict__ cidx,
                        const int*   __restrict__ partners,
                        float*       __restrict__ out) {
    int i = blockIdx.x * blockDim.x + threadIdx.x;
    if (i >= NTOT) return;

    int b  = abatch[i];
    int ci = cidx[i];
    const float* cp = coords + ((long)b * MPER + ci) * 3;
    float x = cp[0], y = cp[1], z = cp[2];
    float sq = (x * x + y * y) + z * z;          // mimic reference sum order
    bool valid = (x != PAD_F);
    g_gat[i] = make_float4(x, y, z, valid ? sq : 3e30f);

    #pragma unroll
    for (int k = 0; k < 2; k++) {
        int p = partners[i * 2 + k];
        float px, py, pz;
        if (p == PAD_I) {
            px = PAD_F; py = PAD_F; pz = PAD_F;
        } else {
            const float* pp = coords + ((long)b * MPER + p) * 3;
            px = pp[0]; py = pp[1]; pz = pp[2];
        }
        float* o = out + (long)i * 8 + 2 + 3 * k;
        o[0] = px; o[1] = py; o[2] = pz;
    }
}

// ---------------------------------------------------------------------------
// Kernel 2: pair distances, j-split for occupancy + 4-row register blocking
//   grid = 32 row-blocks * 16 j-chunks = 512 blocks, 128 threads.
//   Each thread owns 4 i-rows (strided by 128) against one 256-j chunk.
// ---------------------------------------------------------------------------
#define PT_THREADS 128
#define RPT 4
#define ROWS_PER_BLOCK (PT_THREADS * RPT)   // 512 (8 blocks per batch row-dim)

__global__ void __launch_bounds__(PT_THREADS)
ff_pairs() {
    __shared__ float4 sh[JCHUNK];

    int rb = blockIdx.x >> 4;          // / JSPLIT : row-block 0..31
    int jc = blockIdx.x & 15;          // % JSPLIT : j-chunk  0..15
    int b  = rb >> 3;                  // 8 row-blocks per batch
    int jbase = b * MPER + jc * JCHUNK;

    for (int t = threadIdx.x; t < JCHUNK; t += PT_THREADS)
        sh[t] = g_gat[jbase + t];
    __syncthreads();

    int row0 = rb * ROWS_PER_BLOCK + threadIdx.x;
    float4 me[RPT];
    float  sum[RPT];
    #pragma unroll
    for (int k = 0; k < RPT; k++) {
        me[k]  = g_gat[row0 + k * PT_THREADS];
        sum[k] = 0.0f;
    }

    #pragma unroll 2
    for (int j = 0; j < JCHUNK; j++) {
        float4 o = sh[j];
        #pragma unroll
        for (int k = 0; k < RPT; k++) {
            float dot = me[k].x * o.x + me[k].y * o.y + me[k].z * o.z;
            float d2  = fmaf(-2.0f, dot, me[k].w + o.w);
            float dm  = fmaxf(d2, 0.0f) + 1e-12f;
            float dist = sqrtf(dm);
            if (dist <= CUTOFF) sum[k] += dist;
        }
    }

    #pragma unroll
    for (int k = 0; k < RPT; k++)
        g_partial[jc * NTOT + row0 + k * PT_THREADS] = sum[k];
}

// ---------------------------------------------------------------------------
// Kernel 2b: deterministic reduction of j-chunk partials (out col 1)
// ---------------------------------------------------------------------------
__global__ void ff_reduce(float* __restrict__ out) {
    int i = blockIdx.x * blockDim.x + threadIdx.x;
    if (i >= NTOT) return;
    float s = 0.0f;
    #pragma unroll
    for (int c = 0; c < JSPLIT; c++)
        s += g_partial[c * NTOT + i];
    out[(long)i * 8 + 1] = s;
}

// ---------------------------------------------------------------------------
// Kernel 3: dihedral angles (out col 0)
// ---------------------------------------------------------------------------
__device__ __forceinline__ float3 f3sub(float4 a, float4 b) {
    return make_float3(a.x - b.x, a.y - b.y, a.z - b.z);
}
__device__ __forceinline__ float3 f3cross(float3 a, float3 b) {
    return make_float3(a.y * b.z - a.z * b.y,
                       a.z * b.x - a.x * b.z,
                       a.x * b.y - a.y * b.x);
}
__device__ __forceinline__ float f3dot(float3 a, float3 b) {
    return a.x * b.x + a.y * b.y + a.z * b.z;
}

__global__ void ff_dihedral(const int* __restrict__ aidx,
                            float*     __restrict__ out) {
    int i = blockIdx.x * blockDim.x + threadIdx.x;
    if (i >= NTOT) return;

    int i0 = aidx[i * 4 + 0];
    int i1 = aidx[i * 4 + 1];
    int i2 = aidx[i * 4 + 2];
    int i3 = aidx[i * 4 + 3];

    if (i0 == PAD_I || i1 == PAD_I || i2 == PAD_I || i3 == PAD_I) {
        out[(long)i * 8] = PAD_F;
        return;
    }

    float4 p1 = g_gat[i0];
    float4 p2 = g_gat[i1];
    float4 p3 = g_gat[i2];
    float4 p4 = g_gat[i3];

    float3 b1 = f3sub(p2, p1);
    float3 b2 = f3sub(p3, p2);
    float3 b3 = f3sub(p4, p3);

    float3 n1 = f3cross(b1, b2);
    float3 n2 = f3cross(b2, b3);

    float nb2 = sqrtf((b2.x * b2.x + b2.y * b2.y) + b2.z * b2.z);
    float inv = 1.0f / (nb2 + 1e-12f);
    float3 b2n = make_float3(b2.x * inv, b2.y * inv, b2.z * inv);

    float3 m1 = f3cross(n1, b2n);

    float xv = f3dot(n1, n2);
    float yv = f3dot(m1, n2);

    out[(long)i * 8] = atan2f(yv, xv);
}

// ---------------------------------------------------------------------------
extern "C" void kernel_launch(void* const* d_in, const int* in_sizes, int n_in,
                              void* d_out, int out_size) {
    const float* coords   = (const float*)d_in[0];
    const int*   abatch   = (const int*)  d_in[1];
    const int*   cidx     = (const int*)  d_in[2];
    const int*   partners = (const int*)  d_in[3];
    const int*   aidx     = (const int*)  d_in[4];
    float*       out      = (float*)d_out;

    ff_prep<<<(NTOT + 255) / 256, 256>>>(coords, abatch, cidx, partners, out);
    ff_pairs<<<32 * JSPLIT, PT_THREADS>>>();
    ff_reduce<<<(NTOT + 255) / 256, 256>>>(out);
    ff_dihedral<<<(NTOT + 255) / 256, 256>>>(aidx, out);
}

// round 7
// speedup vs baseline: 8.0582x; 1.4652x over previous
#include <cuda_runtime.h>
#include <cuda_bf16.h>

#define BATCH 4
#define MPER  4096
#define NTOT  (BATCH * MPER)
#define PAD_I (-999)
#define PAD_F (-999.0f)
#define CUT2  49.0f

// Gathered coordinates: x, y, z, sq (sq replaced by 3e30 marker when invalid)
__device__ float4 g_gat[NTOT];

// Partial row-sums for the pair kernel: [JSPLIT][NTOT]
#define JSPLIT 16
#define JCHUNK (MPER / JSPLIT)        // 256
__device__ float g_partial[JSPLIT * NTOT];

// ---------------------------------------------------------------------------
// Kernel 1: gather coords (+sq), write partner columns (out cols 2..7)
// ---------------------------------------------------------------------------
__global__ void ff_prep(const float* __restrict__ coords,
                        const int*   __restrict__ abatch,
                        const int*   __restrict__ cidx,
                        const int*   __restrict__ partners,
                        float*       __restrict__ out) {
    int i = blockIdx.x * blockDim.x + threadIdx.x;
    if (i >= NTOT) return;

    int b  = abatch[i];
    int ci = cidx[i];
    const float* cp = coords + ((long)b * MPER + ci) * 3;
    float x = cp[0], y = cp[1], z = cp[2];
    float sq = (x * x + y * y) + z * z;
    bool valid = (x != PAD_F);
    g_gat[i] = make_float4(x, y, z, valid ? sq : 3e30f);

    #pragma unroll
    for (int k = 0; k < 2; k++) {
        int p = partners[i * 2 + k];
        float px, py, pz;
        if (p == PAD_I) {
            px = PAD_F; py = PAD_F; pz = PAD_F;
        } else {
            const float* pp = coords + ((long)b * MPER + p) * 3;
            px = pp[0]; py = pp[1]; pz = pp[2];
        }
        float* o = out + (long)i * 8 + 2 + 3 * k;
        o[0] = px; o[1] = py; o[2] = pz;
    }
}

// ---------------------------------------------------------------------------
// Kernel 2: pair distances. Fast path = cutoff test on squared distance
// (5 instr/pair); sqrt only when some lane in the warp has a hit (~0.3% of
// pairs). grid = 32 row-blocks * 16 j-chunks = 512 blocks, 128 threads,
// 4 i-rows per thread.
// ---------------------------------------------------------------------------
#define PT_THREADS 128
#define RPT 4
#define ROWS_PER_BLOCK (PT_THREADS * RPT)   // 512

__global__ void __launch_bounds__(PT_THREADS)
ff_pairs() {
    __shared__ float4 sh[JCHUNK];

    int rb = blockIdx.x >> 4;          // row-block 0..31
    int jc = blockIdx.x & 15;          // j-chunk  0..15
    int b  = rb >> 3;                  // 8 row-blocks per batch
    int jbase = b * MPER + jc * JCHUNK;

    for (int t = threadIdx.x; t < JCHUNK; t += PT_THREADS)
        sh[t] = g_gat[jbase + t];
    __syncthreads();

    int row0 = rb * ROWS_PER_BLOCK + threadIdx.x;
    float4 me[RPT];
    float  cmp[RPT];                   // 49 - sq_i  (NaN-free: sq finite or 3e30)
    float  sum[RPT];
    #pragma unroll
    for (int k = 0; k < RPT; k++) {
        me[k]  = g_gat[row0 + k * PT_THREADS];
        cmp[k] = CUT2 - me[k].w;       // invalid row -> -3e30, nothing passes
        sum[k] = 0.0f;
    }

    #pragma unroll 2
    for (int j = 0; j < JCHUNK; j++) {
        float4 o = sh[j];
        float d2[RPT];
        bool  p[RPT];
        #pragma unroll
        for (int k = 0; k < RPT; k++) {
            float dot = me[k].x * o.x + me[k].y * o.y + me[k].z * o.z;
            d2[k] = fmaf(-2.0f, dot, o.w);       // sq_j - 2*dot
            p[k]  = (d2[k] <= cmp[k]);           // <=> sq_i + sq_j - 2dot <= 49
        }
        bool any = (p[0] | p[1]) | (p[2] | p[3]);
        if (__any_sync(0xffffffffu, any)) {
            #pragma unroll
            for (int k = 0; k < RPT; k++) {
                if (p[k]) {
                    float dm = fmaxf(d2[k] + me[k].w, 0.0f) + 1e-12f;
                    sum[k] += sqrtf(dm);
                }
            }
        }
    }

    #pragma unroll
    for (int k = 0; k < RPT; k++)
        g_partial[jc * NTOT + row0 + k * PT_THREADS] = sum[k];
}

// ---------------------------------------------------------------------------
// Kernel 3 (epilogue): reduce j-chunk partials (col 1) + dihedral (col 0)
// ---------------------------------------------------------------------------
__device__ __forceinline__ float3 f3sub(float4 a, float4 b) {
    return make_float3(a.x - b.x, a.y - b.y, a.z - b.z);
}
__device__ __forceinline__ float3 f3cross(float3 a, float3 b) {
    return make_float3(a.y * b.z - a.z * b.y,
                       a.z * b.x - a.x * b.z,
                       a.x * b.y - a.y * b.x);
}
__device__ __forceinline__ float f3dot(float3 a, float3 b) {
    return a.x * b.x + a.y * b.y + a.z * b.z;
}

__global__ void ff_epilogue(const int* __restrict__ aidx,
                            float*     __restrict__ out) {
    int i = blockIdx.x * blockDim.x + threadIdx.x;
    if (i >= NTOT) return;

    // --- neighbor-sum reduction ---
    float s = 0.0f;
    #pragma unroll
    for (int c = 0; c < JSPLIT; c++)
        s += g_partial[c * NTOT + i];
    out[(long)i * 8 + 1] = s;

    // --- dihedral ---
    int i0 = aidx[i * 4 + 0];
    int i1 = aidx[i * 4 + 1];
    int i2 = aidx[i * 4 + 2];
    int i3 = aidx[i * 4 + 3];

    if (i0 == PAD_I || i1 == PAD_I || i2 == PAD_I || i3 == PAD_I) {
        out[(long)i * 8] = PAD_F;
        return;
    }

    float4 p1 = g_gat[i0];
    float4 p2 = g_gat[i1];
    float4 p3 = g_gat[i2];
    float4 p4 = g_gat[i3];

    float3 b1 = f3sub(p2, p1);
    float3 b2 = f3sub(p3, p2);
    float3 b3 = f3sub(p4, p3);

    float3 n1 = f3cross(b1, b2);
    float3 n2 = f3cross(b2, b3);

    float nb2 = sqrtf((b2.x * b2.x + b2.y * b2.y) + b2.z * b2.z);
    float inv = 1.0f / (nb2 + 1e-12f);
    float3 b2n = make_float3(b2.x * inv, b2.y * inv, b2.z * inv);

    float3 m1 = f3cross(n1, b2n);

    float xv = f3dot(n1, n2);
    float yv = f3dot(m1, n2);

    out[(long)i * 8] = atan2f(yv, xv);
}

// ---------------------------------------------------------------------------
extern "C" void kernel_launch(void* const* d_in, const int* in_sizes, int n_in,
                              void* d_out, int out_size) {
    const float* coords   = (const float*)d_in[0];
    const int*   abatch   = (const int*)  d_in[1];
    const int*   cidx     = (const int*)  d_in[2];
    const int*   partners = (const int*)  d_in[3];
    const int*   aidx     = (const int*)  d_in[4];
    float*       out      = (float*)d_out;

    ff_prep<<<(NTOT + 255) / 256, 256>>>(coords, abatch, cidx, partners, out);
    ff_pairs<<<32 * JSPLIT, PT_THREADS>>>();
    ff_epilogue<<<(NTOT + 255) / 256, 256>>>(aidx, out);
}

// round 9
// speedup vs baseline: 13.2037x; 1.6386x over previous
#include <cuda_runtime.h>
#include <cuda_bf16.h>
#include <cstdint>

#define BATCH 4
#define MPER  4096
#define NTOT  (BATCH * MPER)
#define PAD_I (-999)
#define PAD_F (-999.0f)
#define CUT2  49.0f

// Gathered coordinates: x, y, z, sq (sq replaced by 3e30 marker when invalid)
__device__ float4 g_gat[NTOT];

// Partial row-sums for the pair kernel: [JSPLIT][NTOT]
#define JSPLIT 16
#define JCHUNK (MPER / JSPLIT)        // 256 j's per chunk = 128 packed jj's
__device__ float g_partial[JSPLIT * NTOT];

// ---------------- packed f32x2 helpers (Blackwell) -------------------------
__device__ __forceinline__ uint64_t pk2(float f) {
    uint64_t r; uint32_t u = __float_as_uint(f);
    asm("mov.b64 %0, {%1, %1};" : "=l"(r) : "r"(u));
    return r;
}
__device__ __forceinline__ uint64_t pfma(uint64_t a, uint64_t b, uint64_t c) {
    uint64_t r;
    asm("fma.rn.f32x2 %0, %1, %2, %3;" : "=l"(r) : "l"(a), "l"(b), "l"(c));
    return r;
}

// ---------------------------------------------------------------------------
// Kernel 1: gather coords (+sq), write partner columns (out cols 2..7)
// ---------------------------------------------------------------------------
__global__ void ff_prep(const float* __restrict__ coords,
                        const int*   __restrict__ abatch,
                        const int*   __restrict__ cidx,
                        const int*   __restrict__ partners,
                        float*       __restrict__ out) {
    int i = blockIdx.x * blockDim.x + threadIdx.x;
    if (i >= NTOT) return;

    int b  = abatch[i];
    int ci = cidx[i];
    const float* cp = coords + ((long)b * MPER + ci) * 3;
    float x = cp[0], y = cp[1], z = cp[2];
    float sq = (x * x + y * y) + z * z;
    bool valid = (x != PAD_F);
    g_gat[i] = make_float4(x, y, z, valid ? sq : 3e30f);

    #pragma unroll
    for (int k = 0; k < 2; k++) {
        int p = partners[i * 2 + k];
        float px, py, pz;
        if (p == PAD_I) {
            px = PAD_F; py = PAD_F; pz = PAD_F;
        } else {
            const float* pp = coords + ((long)b * MPER + p) * 3;
            px = pp[0]; py = pp[1]; pz = pp[2];
        }
        float* o = out + (long)i * 8 + 2 + 3 * k;
        o[0] = px; o[1] = py; o[2] = pz;
    }
}

// ---------------------------------------------------------------------------
// Kernel 2: pair screening with packed f32x2 + bitmask replay of hits.
//   grid = 32 row-blocks * 16 j-chunks = 512 blocks, 128 threads,
//   4 i-rows per thread, 2 j's per packed op.
//   Tail: dihedral for 32 rows per block.
// ---------------------------------------------------------------------------
#define PT_THREADS 128
#define RPT 4
#define ROWS_PER_BLOCK (PT_THREADS * RPT)   // 512

__device__ __forceinline__ float3 f3sub(float4 a, float4 b) {
    return make_float3(a.x - b.x, a.y - b.y, a.z - b.z);
}
__device__ __forceinline__ float3 f3cross(float3 a, float3 b) {
    return make_float3(a.y * b.z - a.z * b.y,
                       a.z * b.x - a.x * b.z,
                       a.x * b.y - a.y * b.x);
}
__device__ __forceinline__ float f3dot(float3 a, float3 b) {
    return a.x * b.x + a.y * b.y + a.z * b.z;
}

__global__ void __launch_bounds__(PT_THREADS)
ff_pairs(const int* __restrict__ aidx, float* __restrict__ out) {
    // 2 float4 per packed jj: [x0 x1 y0 y1][z0 z1 w0-49 w1-49]
    __shared__ float4 sh[2 * (JCHUNK / 2)];

    int rb = blockIdx.x >> 4;          // row-block 0..31
    int jc = blockIdx.x & 15;          // j-chunk  0..15
    int b  = rb >> 3;                  // 8 row-blocks per batch
    int jbase = b * MPER + jc * JCHUNK;

    {
        int t = threadIdx.x;           // exactly 128 packed slots
        float4 a0 = g_gat[jbase + 2 * t];
        float4 a1 = g_gat[jbase + 2 * t + 1];
        sh[2 * t]     = make_float4(a0.x, a1.x, a0.y, a1.y);
        sh[2 * t + 1] = make_float4(a0.z, a1.z, a0.w - CUT2, a1.w - CUT2);
    }
    __syncthreads();

    int row0 = rb * ROWS_PER_BLOCK + threadIdx.x;
    float4   me[RPT];
    float    cmp[RPT];                 // 49 - sq_i
    float    sum[RPT];
    uint64_t mx[RPT], my2[RPT], mz2[RPT], mh[RPT];
    #pragma unroll
    for (int k = 0; k < RPT; k++) {
        me[k]  = g_gat[row0 + k * PT_THREADS];
        cmp[k] = CUT2 - me[k].w;
        sum[k] = 0.0f;
        mx[k]  = pk2(me[k].x);
        my2[k] = pk2(me[k].y);
        mz2[k] = pk2(me[k].z);
        mh[k]  = pk2(-0.5f * me[k].w); // seed: dot - sq_i/2
    }
    const uint64_t NEG2 = pk2(-2.0f);
    const uint32_t sb   = (uint32_t)__cvta_generic_to_shared(sh);

    #pragma unroll
    for (int g = 0; g < 4; g++) {
        uint32_t mask = 0;
        #pragma unroll 4
        for (int jj = 0; jj < 32; jj++) {
            uint32_t ad = sb + (uint32_t)(g * 32 + jj) * 32u;
            uint64_t ux, uy, uz, uw;
            asm("ld.shared.v2.u64 {%0, %1}, [%2];"
                : "=l"(ux), "=l"(uy) : "r"(ad));
            asm("ld.shared.v2.u64 {%0, %1}, [%2];"
                : "=l"(uz), "=l"(uw) : "r"(ad + 16u));
            uint32_t orr = 0;
            #pragma unroll
            for (int k = 0; k < RPT; k++) {
                uint64_t t = pfma(mz2[k], uz, mh[k]);
                t = pfma(my2[k], uy, t);
                t = pfma(mx[k],  ux, t);
                uint64_t s = pfma(NEG2, t, uw);   // D - 49, packed x2
                orr |= (uint32_t)s | (uint32_t)(s >> 32);
            }
            mask = (mask << 1) | (orr >> 31);
        }
        // replay flagged jj's (hits are ~0.3% of pairs)
        while (mask) {
            int jjl = __clz(mask);
            mask &= ~(0x80000000u >> jjl);
            int idx = g * 32 + jjl;
            float4 A  = sh[2 * idx];       // x0 x1 y0 y1
            float4 Bv = sh[2 * idx + 1];   // z0 z1 w0-49 w1-49
            float w0 = Bv.z + CUT2;        // exact round-trip
            float w1 = Bv.w + CUT2;
            #pragma unroll
            for (int k = 0; k < RPT; k++) {
                float t0 = me[k].z * Bv.x;
                t0 = fmaf(me[k].y, A.z, t0);
                t0 = fmaf(me[k].x, A.x, t0);
                float d20 = fmaf(-2.0f, t0, w0);
                if (d20 <= cmp[k])
                    sum[k] += sqrtf(fmaxf(d20 + me[k].w, 0.0f) + 1e-12f);

                float t1 = me[k].z * Bv.y;
                t1 = fmaf(me[k].y, A.w, t1);
                t1 = fmaf(me[k].x, A.y, t1);
                float d21 = fmaf(-2.0f, t1, w1);
                if (d21 <= cmp[k])
                    sum[k] += sqrtf(fmaxf(d21 + me[k].w, 0.0f) + 1e-12f);
            }
        }
    }

    #pragma unroll
    for (int k = 0; k < RPT; k++)
        g_partial[jc * NTOT + row0 + k * PT_THREADS] = sum[k];

    // ---- dihedral tail: 32 rows per block (512 blocks * 32 = NTOT) ----
    if (threadIdx.x < 32) {
        int i = blockIdx.x * 32 + threadIdx.x;

        int i0 = aidx[i * 4 + 0];
        int i1 = aidx[i * 4 + 1];
        int i2 = aidx[i * 4 + 2];
        int i3 = aidx[i * 4 + 3];

        if (i0 == PAD_I || i1 == PAD_I || i2 == PAD_I || i3 == PAD_I) {
            out[(long)i * 8] = PAD_F;
            return;
        }

        float4 p1 = g_gat[i0];
        float4 p2 = g_gat[i1];
        float4 p3 = g_gat[i2];
        float4 p4 = g_gat[i3];

        float3 b1 = f3sub(p2, p1);
        float3 b2 = f3sub(p3, p2);
        float3 b3 = f3sub(p4, p3);

        float3 n1 = f3cross(b1, b2);
        float3 n2 = f3cross(b2, b3);

        float nb2 = sqrtf((b2.x * b2.x + b2.y * b2.y) + b2.z * b2.z);
        float inv = 1.0f / (nb2 + 1e-12f);
        float3 b2n = make_float3(b2.x * inv, b2.y * inv, b2.z * inv);

        float3 m1 = f3cross(n1, b2n);

        float xv = f3dot(n1, n2);
        float yv = f3dot(m1, n2);

        out[(long)i * 8] = atan2f(yv, xv);
    }
}

// ---------------------------------------------------------------------------
// Kernel 3: deterministic reduction of j-chunk partials (out col 1)
// ---------------------------------------------------------------------------
__global__ void ff_reduce(float* __restrict__ out) {
    int i = blockIdx.x * blockDim.x + threadIdx.x;
    if (i >= NTOT) return;
    float s = 0.0f;
    #pragma unroll
    for (int c = 0; c < JSPLIT; c++)
        s += g_partial[c * NTOT + i];
    out[(long)i * 8 + 1] = s;
}

// ---------------------------------------------------------------------------
extern "C" void kernel_launch(void* const* d_in, const int* in_sizes, int n_in,
                              void* d_out, int out_size) {
    const float* coords   = (const float*)d_in[0];
    const int*   abatch   = (const int*)  d_in[1];
    const int*   cidx     = (const int*)  d_in[2];
    const int*   partners = (const int*)  d_in[3];
    const int*   aidx     = (const int*)  d_in[4];
    float*       out      = (float*)d_out;

    ff_prep<<<NTOT / 128, 128>>>(coords, abatch, cidx, partners, out);
    ff_pairs<<<32 * JSPLIT, PT_THREADS>>>(aidx, out);
    ff_reduce<<<NTOT / 256, 256>>>(out);
}